// round 7
// baseline (speedup 1.0000x reference)
#include <cuda_runtime.h>
#include <cuda_bf16.h>
#include <stdint.h>
#include <math.h>
#include <string.h>

// Problem constants
#define N_ROWS 65536      // B*H*W = 16*64*64
#define N_CODES 2048
#define CDIM 64
#define BM 128
#define N_TILES (N_ROWS / BM)      // 512
#define E_TILES (N_CODES / BM)     // 16

// Output layout: concat(z_q_out[B,C,H,W], loss, perplexity, indices) as fp32
#define O_LOSS 4194304
#define O_PERP 4194305
#define O_IDX  4194306

// smem geometry for the MMA kernel
#define ROWB 160                    // padded bytes per 128-byte row
#define PLANE (128 * ROWB)          // 20480 B per plane tile
#define DSMEM_REQ (9 * PLANE)       // A: 3 planes, B: 2 x 3 planes = 184320 B

// ---------------- scratch (device globals; no allocations allowed) --------
__device__ int   g_idx_buf[N_ROWS];
__device__ int   g_counts[N_CODES];
__device__ float g_sumsq;

// bf16 split planes, dense 16KB tiles (128 rows x 64 k), k-halves interleaved
__device__ uint4 g_z0[N_TILES * 1024];
__device__ uint4 g_z1[N_TILES * 1024];
__device__ uint4 g_z2[N_TILES * 1024];
__device__ uint4 g_e0[E_TILES * 1024];
__device__ uint4 g_e1[E_TILES * 1024];
__device__ uint4 g_e2[E_TILES * 1024];

// ---------------- helpers -------------------------------------------------
__device__ __forceinline__ uint32_t smem_u32(const void* p) {
    uint32_t a;
    asm("{ .reg .u64 t; cvta.to.shared.u64 t, %1; cvt.u32.u64 %0, t; }"
        : "=r"(a) : "l"(p));
    return a;
}

__device__ __forceinline__ void cp16(uint32_t dst, const void* src) {
    asm volatile("cp.async.cg.shared.global [%0], [%1], 16;"
                 :: "r"(dst), "l"(src) : "memory");
}
#define CP_COMMIT() asm volatile("cp.async.commit_group;" ::: "memory")
#define CP_WAIT1()  asm volatile("cp.async.wait_group 1;" ::: "memory")
#define CP_WAIT0()  asm volatile("cp.async.wait_group 0;" ::: "memory")

#define MMA16816(cc, a0, a1, a2, a3, bb0, bb1) \
    asm("mma.sync.aligned.m16n8k16.row.col.f32.bf16.bf16.f32 " \
        "{%0,%1,%2,%3}, {%4,%5,%6,%7}, {%8,%9}, {%0,%1,%2,%3};" \
        : "+f"((cc)[0]), "+f"((cc)[1]), "+f"((cc)[2]), "+f"((cc)[3]) \
        : "r"(a0), "r"(a1), "r"(a2), "r"(a3), "r"(bb0), "r"(bb1))

// ---------------- bf16 triple split --------------------------------------
__device__ __forceinline__ void split3(float v, unsigned short& u0,
                                       unsigned short& u1, unsigned short& u2) {
    __nv_bfloat16 h0 = __float2bfloat16(v);
    float r1 = v - __bfloat162float(h0);
    __nv_bfloat16 h1 = __float2bfloat16(r1);
    float r2 = r1 - __bfloat162float(h1);
    __nv_bfloat16 h2 = __float2bfloat16(r2);
    memcpy(&u0, &h0, 2); memcpy(&u1, &h1, 2); memcpy(&u2, &h2, 2);
}
__device__ __forceinline__ uint32_t pack2(unsigned short lo, unsigned short hi) {
    return (uint32_t)lo | ((uint32_t)hi << 16);
}
__device__ __forceinline__ uint4 pack_u4(const unsigned short* lo4,
                                         const unsigned short* hi4) {
    return make_uint4(pack2(lo4[0], lo4[1]), pack2(hi4[0], hi4[1]),
                      pack2(lo4[2], lo4[3]), pack2(hi4[2], hi4[3]));
}

// ---------------- kernel: split + interleave z ---------------------------
__global__ void __launch_bounds__(128)
vq_split_z(const float* __restrict__ z) {
    __shared__ float s[64][129];
    const int tile = blockIdx.x;
    const int n0 = tile * BM;
    const int b = n0 >> 12, p0 = n0 & 4095;
    const float* src = z + ((size_t)b * CDIM) * 4096 + p0;
    const int i = threadIdx.x;
#pragma unroll 8
    for (int c = 0; c < 64; c++) s[c][i] = src[(size_t)c * 4096 + i];
    __syncthreads();

#pragma unroll
    for (int j = 0; j < 8; j++) {
        int a = (j >> 1) * 16 + (j & 1) * 4;
        unsigned short l0[4], l1[4], l2[4], h0[4], h1[4], h2[4];
#pragma unroll
        for (int q = 0; q < 4; q++) {
            split3(s[a + q][i], l0[q], l1[q], l2[q]);
            split3(s[a + 8 + q][i], h0[q], h1[q], h2[q]);
        }
        int idx = tile * 1024 + i * 8 + j;
        g_z0[idx] = pack_u4(l0, h0);
        g_z1[idx] = pack_u4(l1, h1);
        g_z2[idx] = pack_u4(l2, h2);
    }
}

// ---------------- kernel: split + interleave codebook --------------------
__global__ void __launch_bounds__(128)
vq_split_cb(const float* __restrict__ cb) {
    const int tile = blockIdx.x;
    const int i = threadIdx.x;
    float v[64];
    const float4* src = (const float4*)(cb + (size_t)(tile * BM + i) * CDIM);
#pragma unroll
    for (int t = 0; t < 16; t++) {
        float4 x = src[t];
        v[t * 4] = x.x; v[t * 4 + 1] = x.y; v[t * 4 + 2] = x.z; v[t * 4 + 3] = x.w;
    }
#pragma unroll
    for (int j = 0; j < 8; j++) {
        int a = (j >> 1) * 16 + (j & 1) * 4;
        unsigned short l0[4], l1[4], l2[4], h0[4], h1[4], h2[4];
#pragma unroll
        for (int q = 0; q < 4; q++) {
            split3(v[a + q], l0[q], l1[q], l2[q]);
            split3(v[a + 8 + q], h0[q], h1[q], h2[q]);
        }
        int idx = tile * 1024 + i * 8 + j;
        g_e0[idx] = pack_u4(l0, h0);
        g_e1[idx] = pack_u4(l1, h1);
        g_e2[idx] = pack_u4(l2, h2);
    }
}

__global__ void vq_init() {
    for (int i = threadIdx.x; i < N_CODES; i += blockDim.x) g_counts[i] = 0;
    if (threadIdx.x == 0) g_sumsq = 0.0f;
}

// ---------------- kernel: mma.sync GEMM + per-row argmax -----------------
// Emulated fp32 via bf16x3: logits = z0e0+z0e1+z1e0+z1e1+z0e2+z2e0.
// CTA: 128 rows x (16 chunks of 128 codes). 16 warps, warp tile 32x32.
__global__ void __launch_bounds__(512, 1)
vq_mma(float* __restrict__ out) {
    extern __shared__ char dsm[];
    const int tid = threadIdx.x;
    const int w = tid >> 5, lane = tid & 31;
    const int g = lane >> 2, q = lane & 3;
    const int wm = (w & 3) * 32, wn = (w >> 2) * 32;
    const int tile = blockIdx.x;

    const uint32_t sA = smem_u32(dsm);
    const uint32_t sB = sA + 3 * PLANE;

    // prologue: A tiles + B chunk 0 (one commit group)
    {
        const uint4* zs[3] = {g_z0 + tile * 1024, g_z1 + tile * 1024,
                              g_z2 + tile * 1024};
#pragma unroll
        for (int s = 0; s < 6; s++) {
            int t = tid + 512 * s;
            int pl = t >> 10, rem = t & 1023, r = rem >> 3, j = rem & 7;
            cp16(sA + pl * PLANE + r * ROWB + j * 16, zs[pl] + rem);
        }
        const uint4* es[3] = {g_e0, g_e1, g_e2};
#pragma unroll
        for (int s = 0; s < 6; s++) {
            int t = tid + 512 * s;
            int pl = t >> 10, rem = t & 1023, r = rem >> 3, j = rem & 7;
            cp16(sB + pl * PLANE + r * ROWB + j * 16, es[pl] + rem);
        }
        CP_COMMIT();
    }

    const int TA[6] = {0, 0, 1, 1, 0, 2};
    const int TB[6] = {0, 1, 0, 1, 2, 0};

    float bv[4];
    int   bi[4];
#pragma unroll
    for (int e = 0; e < 4; e++) { bv[e] = -3.4e38f; bi[e] = 0; }

    for (int ch = 0; ch < 16; ch++) {
        if (ch < 15) {   // prefetch next B chunk into other buffer
            const uint4* es[3] = {g_e0 + (ch + 1) * 1024, g_e1 + (ch + 1) * 1024,
                                  g_e2 + (ch + 1) * 1024};
            uint32_t dstb = sB + ((ch + 1) & 1) * (3 * PLANE);
#pragma unroll
            for (int s = 0; s < 6; s++) {
                int t = tid + 512 * s;
                int pl = t >> 10, rem = t & 1023, r = rem >> 3, j = rem & 7;
                cp16(dstb + pl * PLANE + r * ROWB + j * 16, es[pl] + rem);
            }
            CP_COMMIT();
            CP_WAIT1();
        } else {
            CP_WAIT0();
        }
        __syncthreads();

        const char* bbuf = dsm + 3 * PLANE + (ch & 1) * (3 * PLANE);

        float c[2][4][4];
#pragma unroll
        for (int mi = 0; mi < 2; mi++)
#pragma unroll
            for (int ni = 0; ni < 4; ni++)
#pragma unroll
                for (int e = 0; e < 4; e++) c[mi][ni][e] = 0.0f;

#pragma unroll
        for (int p = 0; p < 6; p++) {
            const char* Ap = dsm + TA[p] * PLANE;
            const char* Bp = bbuf + TB[p] * PLANE;
#pragma unroll
            for (int ks = 0; ks < 4; ks++) {
                int koff = ks * 32 + q * 8;
                uint2 bb[4];
#pragma unroll
                for (int ni = 0; ni < 4; ni++)
                    bb[ni] = *(const uint2*)(Bp + (wn + 8 * ni + g) * ROWB + koff);
#pragma unroll
                for (int mi = 0; mi < 2; mi++) {
                    const char* ab = Ap + (wm + 16 * mi + g) * ROWB + koff;
                    uint2 alo = *(const uint2*)(ab);
                    uint2 ahi = *(const uint2*)(ab + 8 * ROWB);
#pragma unroll
                    for (int ni = 0; ni < 4; ni++)
                        MMA16816(c[mi][ni], alo.x, ahi.x, alo.y, ahi.y,
                                 bb[ni].x, bb[ni].y);
                }
            }
        }

        // fold chunk into running argmax (ascending candidate order -> strict >)
        const int cb0 = ch * 128 + wn + 2 * q;
#pragma unroll
        for (int mi = 0; mi < 2; mi++) {
            const int lo = mi * 2, hi = mi * 2 + 1;
#pragma unroll
            for (int ni = 0; ni < 4; ni++) {
                int ce = cb0 + 8 * ni;
                if (c[mi][ni][0] > bv[lo]) { bv[lo] = c[mi][ni][0]; bi[lo] = ce; }
                if (c[mi][ni][1] > bv[lo]) { bv[lo] = c[mi][ni][1]; bi[lo] = ce + 1; }
                if (c[mi][ni][2] > bv[hi]) { bv[hi] = c[mi][ni][2]; bi[hi] = ce; }
                if (c[mi][ni][3] > bv[hi]) { bv[hi] = c[mi][ni][3]; bi[hi] = ce + 1; }
            }
        }
        __syncthreads();
    }

    // quad shuffle reduce (lanes sharing a row differ only in q)
#pragma unroll
    for (int e = 0; e < 4; e++) {
#pragma unroll
        for (int off = 1; off <= 2; off <<= 1) {
            float ov = __shfl_xor_sync(0xffffffffu, bv[e], off);
            int   oi = __shfl_xor_sync(0xffffffffu, bi[e], off);
            if (ov > bv[e] || (ov == bv[e] && oi < bi[e])) { bv[e] = ov; bi[e] = oi; }
        }
    }

    float* sval = (float*)dsm;            // [128][4]
    int*   sidx = (int*)(dsm + 2048);     // [128][4]
    if (q == 0) {
#pragma unroll
        for (int mi = 0; mi < 2; mi++)
#pragma unroll
            for (int h = 0; h < 2; h++) {
                int r = wm + 16 * mi + 8 * h + g;
                sval[r * 4 + (w >> 2)] = bv[mi * 2 + h];
                sidx[r * 4 + (w >> 2)] = bi[mi * 2 + h];
            }
    }
    __syncthreads();
    if (tid < 128) {
        float v = sval[tid * 4];
        int   i2 = sidx[tid * 4];
#pragma unroll
        for (int wg = 1; wg < 4; wg++) {
            float ov = sval[tid * 4 + wg];
            int   oi = sidx[tid * 4 + wg];
            if (ov > v || (ov == v && oi < i2)) { v = ov; i2 = oi; }
        }
        int n = tile * BM + tid;
        g_idx_buf[n] = i2;
        out[O_IDX + n] = (float)i2;
    }
}

// ---------------- kernel: gather + loss + histogram ----------------------
__global__ void __launch_bounds__(256)
vq_gather(const float* __restrict__ z, const float* __restrict__ cb,
          float* __restrict__ out) {
    __shared__ float zq_s[128][65];
    __shared__ int   ids[128];
    __shared__ float wsum[8];
    const int tid = threadIdx.x;
    const int n0 = blockIdx.x * BM;
    const int b  = n0 >> 12;
    const int p0 = n0 & 4095;

    if (tid < 128) {
        int id = g_idx_buf[n0 + tid];
        ids[tid] = id;
        atomicAdd(&g_counts[id], 1);
    }
    __syncthreads();
    {
        int row = tid >> 1, h = tid & 1;
        const float4* src = (const float4*)(cb + (size_t)ids[row] * CDIM + h * 32);
#pragma unroll
        for (int t = 0; t < 8; t++) {
            float4 v = src[t];
            int c = h * 32 + t * 4;
            zq_s[row][c] = v.x; zq_s[row][c + 1] = v.y;
            zq_s[row][c + 2] = v.z; zq_s[row][c + 3] = v.w;
        }
    }
    __syncthreads();

    int i  = tid & 127;
    int c0 = tid >> 7;
    const float* zsrc = z + ((size_t)b * CDIM) * 4096 + p0;
    float* od = out + ((size_t)b * CDIM) * 4096 + p0;
    float lsum = 0.0f;
#pragma unroll
    for (int s = 0; s < 32; s++) {
        int c = c0 + 2 * s;
        float v  = zq_s[i][c];
        float zv = zsrc[(size_t)c * 4096 + i];
        float d  = v - zv;
        lsum += d * d;
        od[(size_t)c * 4096 + i] = v;
    }
    for (int o = 16; o > 0; o >>= 1) lsum += __shfl_down_sync(0xffffffffu, lsum, o);
    if ((tid & 31) == 0) wsum[tid >> 5] = lsum;
    __syncthreads();
    if (tid == 0) {
        float t = 0.0f;
#pragma unroll
        for (int ww = 0; ww < 8; ww++) t += wsum[ww];
        atomicAdd(&g_sumsq, t);
    }
}

// ---------------- kernel: scalars ----------------------------------------
__global__ void vq_final(float* __restrict__ out) {
    __shared__ float red[256];
    const int tid = threadIdx.x;
    float h = 0.0f;
    for (int i = tid; i < N_CODES; i += 256) {
        float e = (float)g_counts[i] * (1.0f / 65536.0f);
        h -= e * logf(e + 1e-10f);
    }
    red[tid] = h;
    __syncthreads();
    for (int o = 128; o > 0; o >>= 1) {
        if (tid < o) red[tid] += red[tid + o];
        __syncthreads();
    }
    if (tid == 0) {
        out[O_LOSS] = 1.25f * g_sumsq / 4194304.0f;
        out[O_PERP] = expf(red[0]);
    }
}

extern "C" void kernel_launch(void* const* d_in, const int* in_sizes, int n_in,
                              void* d_out, int out_size) {
    const float* z  = (const float*)d_in[0];
    const float* cb = (const float*)d_in[1];
    if (n_in >= 2 && in_sizes[0] == N_CODES * CDIM) {
        z  = (const float*)d_in[1];
        cb = (const float*)d_in[0];
    }
    float* out = (float*)d_out;

    cudaFuncSetAttribute(vq_mma, cudaFuncAttributeMaxDynamicSharedMemorySize,
                         DSMEM_REQ);

    vq_split_z<<<N_TILES, 128>>>(z);
    vq_split_cb<<<E_TILES, 128>>>(cb);
    vq_init<<<1, 256>>>();
    vq_mma<<<N_TILES, 512, DSMEM_REQ>>>(out);
    vq_gather<<<N_TILES, 256>>>(z, cb, out);
    vq_final<<<1, 256>>>(out);
    (void)out_size;
}

// round 8
// speedup vs baseline: 1.5232x; 1.5232x over previous
#include <cuda_runtime.h>
#include <cuda_bf16.h>
#include <stdint.h>
#include <math.h>
#include <string.h>

// Problem constants
#define N_ROWS 65536      // B*H*W = 16*64*64
#define N_CODES 2048
#define CDIM 64
#define BM 128
#define N_TILES (N_ROWS / BM)      // 512
#define E_TILES (N_CODES / BM)     // 16

// Output layout: concat(z_q_out[B,C,H,W], loss, perplexity, indices) as fp32
#define O_LOSS 4194304
#define O_PERP 4194305
#define O_IDX  4194306

// smem geometry: plain row-major bf16 rows (128B data) padded to 144B so
// ldmatrix 8-row phases hit distinct 4-bank groups (36r mod 32 = 4r).
#define ROWB 144
#define PLANE (128 * ROWB)          // 18432 B per plane tile
#define DSMEM_REQ (9 * PLANE)       // A: 3 planes, B: 2 x 3 planes = 165888 B

// ---------------- scratch (device globals; no allocations allowed) --------
__device__ int   g_idx_buf[N_ROWS];
__device__ int   g_counts[N_CODES];
__device__ float g_sumsq;

// bf16 split planes, dense 16KB tiles (128 rows x 64 k), PLAIN row-major
__device__ uint4 g_z0[N_TILES * 1024];
__device__ uint4 g_z1[N_TILES * 1024];
__device__ uint4 g_z2[N_TILES * 1024];
__device__ uint4 g_e0[E_TILES * 1024];
__device__ uint4 g_e1[E_TILES * 1024];
__device__ uint4 g_e2[E_TILES * 1024];

// ---------------- helpers -------------------------------------------------
__device__ __forceinline__ uint32_t smem_u32(const void* p) {
    uint32_t a;
    asm("{ .reg .u64 t; cvta.to.shared.u64 t, %1; cvt.u32.u64 %0, t; }"
        : "=r"(a) : "l"(p));
    return a;
}

__device__ __forceinline__ void cp16(uint32_t dst, const void* src) {
    asm volatile("cp.async.cg.shared.global [%0], [%1], 16;"
                 :: "r"(dst), "l"(src) : "memory");
}
#define CP_COMMIT() asm volatile("cp.async.commit_group;" ::: "memory")
#define CP_WAIT1()  asm volatile("cp.async.wait_group 1;" ::: "memory")
#define CP_WAIT0()  asm volatile("cp.async.wait_group 0;" ::: "memory")

__device__ __forceinline__ void ldm4(uint32_t* r, uint32_t addr) {
    asm volatile("ldmatrix.sync.aligned.m8n8.x4.shared.b16 {%0,%1,%2,%3}, [%4];"
                 : "=r"(r[0]), "=r"(r[1]), "=r"(r[2]), "=r"(r[3]) : "r"(addr));
}

#define MMA16816(cc, a0, a1, a2, a3, bb0, bb1) \
    asm("mma.sync.aligned.m16n8k16.row.col.f32.bf16.bf16.f32 " \
        "{%0,%1,%2,%3}, {%4,%5,%6,%7}, {%8,%9}, {%0,%1,%2,%3};" \
        : "+f"((cc)[0]), "+f"((cc)[1]), "+f"((cc)[2]), "+f"((cc)[3]) \
        : "r"(a0), "r"(a1), "r"(a2), "r"(a3), "r"(bb0), "r"(bb1))

// ---------------- bf16 triple split --------------------------------------
__device__ __forceinline__ void split3(float v, unsigned short& u0,
                                       unsigned short& u1, unsigned short& u2) {
    __nv_bfloat16 h0 = __float2bfloat16(v);
    float r1 = v - __bfloat162float(h0);
    __nv_bfloat16 h1 = __float2bfloat16(r1);
    float r2 = r1 - __bfloat162float(h1);
    __nv_bfloat16 h2 = __float2bfloat16(r2);
    memcpy(&u0, &h0, 2); memcpy(&u1, &h1, 2); memcpy(&u2, &h2, 2);
}
__device__ __forceinline__ uint32_t pack2(unsigned short lo, unsigned short hi) {
    return (uint32_t)lo | ((uint32_t)hi << 16);
}

// ---------------- kernel: split z (plain row-major) ----------------------
__global__ void __launch_bounds__(128)
vq_split_z(const float* __restrict__ z) {
    __shared__ float s[64][129];
    const int tile = blockIdx.x;
    const int n0 = tile * BM;
    const int b = n0 >> 12, p0 = n0 & 4095;
    const float* src = z + ((size_t)b * CDIM) * 4096 + p0;
    const int i = threadIdx.x;
#pragma unroll 8
    for (int c = 0; c < 64; c++) s[c][i] = src[(size_t)c * 4096 + i];
    __syncthreads();

#pragma unroll
    for (int j = 0; j < 8; j++) {
        unsigned short u0[8], u1[8], u2[8];
#pragma unroll
        for (int q = 0; q < 8; q++) split3(s[j * 8 + q][i], u0[q], u1[q], u2[q]);
        int idx = tile * 1024 + i * 8 + j;
        g_z0[idx] = make_uint4(pack2(u0[0], u0[1]), pack2(u0[2], u0[3]),
                               pack2(u0[4], u0[5]), pack2(u0[6], u0[7]));
        g_z1[idx] = make_uint4(pack2(u1[0], u1[1]), pack2(u1[2], u1[3]),
                               pack2(u1[4], u1[5]), pack2(u1[6], u1[7]));
        g_z2[idx] = make_uint4(pack2(u2[0], u2[1]), pack2(u2[2], u2[3]),
                               pack2(u2[4], u2[5]), pack2(u2[6], u2[7]));
    }
}

// ---------------- kernel: split codebook (plain row-major) ---------------
__global__ void __launch_bounds__(128)
vq_split_cb(const float* __restrict__ cb) {
    const int tile = blockIdx.x;
    const int i = threadIdx.x;
    float v[64];
    const float4* src = (const float4*)(cb + (size_t)(tile * BM + i) * CDIM);
#pragma unroll
    for (int t = 0; t < 16; t++) {
        float4 x = src[t];
        v[t * 4] = x.x; v[t * 4 + 1] = x.y; v[t * 4 + 2] = x.z; v[t * 4 + 3] = x.w;
    }
#pragma unroll
    for (int j = 0; j < 8; j++) {
        unsigned short u0[8], u1[8], u2[8];
#pragma unroll
        for (int q = 0; q < 8; q++) split3(v[j * 8 + q], u0[q], u1[q], u2[q]);
        int idx = tile * 1024 + i * 8 + j;
        g_e0[idx] = make_uint4(pack2(u0[0], u0[1]), pack2(u0[2], u0[3]),
                               pack2(u0[4], u0[5]), pack2(u0[6], u0[7]));
        g_e1[idx] = make_uint4(pack2(u1[0], u1[1]), pack2(u1[2], u1[3]),
                               pack2(u1[4], u1[5]), pack2(u1[6], u1[7]));
        g_e2[idx] = make_uint4(pack2(u2[0], u2[1]), pack2(u2[2], u2[3]),
                               pack2(u2[4], u2[5]), pack2(u2[6], u2[7]));
    }
}

__global__ void vq_init() {
    for (int i = threadIdx.x; i < N_CODES; i += blockDim.x) g_counts[i] = 0;
    if (threadIdx.x == 0) g_sumsq = 0.0f;
}

// ---------------- kernel: mma.sync GEMM + per-row argmax -----------------
// Emulated fp32 via bf16x3: logits = z0e0+z0e1+z1e0+z1e1+z0e2+z2e0, all six
// products accumulated into ONE accumulator set. 8 warps, warp tile 64x32.
// Operand loads via ldmatrix.x4 (18 smem instr per 96 HMMA per k-step).
__global__ void __launch_bounds__(256, 1)
vq_mma(float* __restrict__ out) {
    extern __shared__ char dsm[];
    const int tid = threadIdx.x;
    const int w = tid >> 5, lane = tid & 31;
    const int g = lane >> 2, q = lane & 3;
    const int mrow = lane & 7, quad = lane >> 3;
    const int wm = (w & 1) * 64, wn = (w >> 1) * 32;
    const int tile = blockIdx.x;

    const uint32_t sA = smem_u32(dsm);
    const uint32_t sB = sA + 3 * PLANE;

    // ldmatrix per-thread intra-plane offsets
    const uint32_t aoff = (uint32_t)(wm + mrow + 8 * (quad & 1)) * ROWB
                        + 16 * (quad >> 1);
    const uint32_t boff = (uint32_t)(wn + mrow + 8 * (quad >> 1)) * ROWB
                        + 16 * (quad & 1);

    // prologue: A tiles + B chunk 0 (one commit group)
    {
        const uint4* zs[3] = {g_z0 + tile * 1024, g_z1 + tile * 1024,
                              g_z2 + tile * 1024};
        for (int t = tid; t < 3072; t += 256) {
            int pl = t >> 10, rem = t & 1023, r = rem >> 3, j = rem & 7;
            cp16(sA + pl * PLANE + r * ROWB + j * 16, zs[pl] + rem);
        }
        const uint4* es[3] = {g_e0, g_e1, g_e2};
        for (int t = tid; t < 3072; t += 256) {
            int pl = t >> 10, rem = t & 1023, r = rem >> 3, j = rem & 7;
            cp16(sB + pl * PLANE + r * ROWB + j * 16, es[pl] + rem);
        }
        CP_COMMIT();
    }

    float bv[8];
    int   bi[8];
#pragma unroll
    for (int e = 0; e < 8; e++) { bv[e] = -3.4e38f; bi[e] = 0; }

    for (int ch = 0; ch < 16; ch++) {
        if (ch < 15) {   // prefetch next B chunk into other buffer
            const uint4* es[3] = {g_e0 + (ch + 1) * 1024, g_e1 + (ch + 1) * 1024,
                                  g_e2 + (ch + 1) * 1024};
            uint32_t dstb = sB + ((ch + 1) & 1) * (3 * PLANE);
            for (int t = tid; t < 3072; t += 256) {
                int pl = t >> 10, rem = t & 1023, r = rem >> 3, j = rem & 7;
                cp16(dstb + pl * PLANE + r * ROWB + j * 16, es[pl] + rem);
            }
            CP_COMMIT();
            CP_WAIT1();
        } else {
            CP_WAIT0();
        }
        __syncthreads();

        const uint32_t bB = sB + (ch & 1) * (3 * PLANE);

        float c[4][4][4];
#pragma unroll
        for (int mi = 0; mi < 4; mi++)
#pragma unroll
            for (int ni = 0; ni < 4; ni++)
#pragma unroll
                for (int e = 0; e < 4; e++) c[mi][ni][e] = 0.0f;

#pragma unroll
        for (int ks = 0; ks < 4; ks++) {
            const uint32_t koff = ks * 32;
            // B fragments for all 3 planes (4 ni each -> 8 regs/plane)
            uint32_t B0[8], B1[8], B2[8];
            ldm4(B0,     bB + 0 * PLANE + boff + koff);
            ldm4(B0 + 4, bB + 0 * PLANE + boff + koff + 16 * ROWB);
            ldm4(B1,     bB + 1 * PLANE + boff + koff);
            ldm4(B1 + 4, bB + 1 * PLANE + boff + koff + 16 * ROWB);
            ldm4(B2,     bB + 2 * PLANE + boff + koff);
            ldm4(B2 + 4, bB + 2 * PLANE + boff + koff + 16 * ROWB);

            uint32_t A[16];
            // z0: products with e0, e1, e2
            ldm4(A,      sA + 0 * PLANE + aoff + koff);
            ldm4(A + 4,  sA + 0 * PLANE + aoff + koff + 16 * ROWB);
            ldm4(A + 8,  sA + 0 * PLANE + aoff + koff + 32 * ROWB);
            ldm4(A + 12, sA + 0 * PLANE + aoff + koff + 48 * ROWB);
#pragma unroll
            for (int mi = 0; mi < 4; mi++)
#pragma unroll
                for (int ni = 0; ni < 4; ni++) {
                    MMA16816(c[mi][ni], A[mi*4], A[mi*4+1], A[mi*4+2], A[mi*4+3],
                             B0[ni*2], B0[ni*2+1]);
                    MMA16816(c[mi][ni], A[mi*4], A[mi*4+1], A[mi*4+2], A[mi*4+3],
                             B1[ni*2], B1[ni*2+1]);
                    MMA16816(c[mi][ni], A[mi*4], A[mi*4+1], A[mi*4+2], A[mi*4+3],
                             B2[ni*2], B2[ni*2+1]);
                }
            // z1: products with e0, e1
            ldm4(A,      sA + 1 * PLANE + aoff + koff);
            ldm4(A + 4,  sA + 1 * PLANE + aoff + koff + 16 * ROWB);
            ldm4(A + 8,  sA + 1 * PLANE + aoff + koff + 32 * ROWB);
            ldm4(A + 12, sA + 1 * PLANE + aoff + koff + 48 * ROWB);
#pragma unroll
            for (int mi = 0; mi < 4; mi++)
#pragma unroll
                for (int ni = 0; ni < 4; ni++) {
                    MMA16816(c[mi][ni], A[mi*4], A[mi*4+1], A[mi*4+2], A[mi*4+3],
                             B0[ni*2], B0[ni*2+1]);
                    MMA16816(c[mi][ni], A[mi*4], A[mi*4+1], A[mi*4+2], A[mi*4+3],
                             B1[ni*2], B1[ni*2+1]);
                }
            // z2: product with e0
            ldm4(A,      sA + 2 * PLANE + aoff + koff);
            ldm4(A + 4,  sA + 2 * PLANE + aoff + koff + 16 * ROWB);
            ldm4(A + 8,  sA + 2 * PLANE + aoff + koff + 32 * ROWB);
            ldm4(A + 12, sA + 2 * PLANE + aoff + koff + 48 * ROWB);
#pragma unroll
            for (int mi = 0; mi < 4; mi++)
#pragma unroll
                for (int ni = 0; ni < 4; ni++)
                    MMA16816(c[mi][ni], A[mi*4], A[mi*4+1], A[mi*4+2], A[mi*4+3],
                             B0[ni*2], B0[ni*2+1]);
        }

        // fold chunk into running argmax (ascending candidate order -> strict >)
        const int cb0 = ch * 128 + wn + 2 * q;
#pragma unroll
        for (int mi = 0; mi < 4; mi++) {
            const int lo = mi * 2, hi = mi * 2 + 1;
#pragma unroll
            for (int ni = 0; ni < 4; ni++) {
                int ce = cb0 + 8 * ni;
                if (c[mi][ni][0] > bv[lo]) { bv[lo] = c[mi][ni][0]; bi[lo] = ce; }
                if (c[mi][ni][1] > bv[lo]) { bv[lo] = c[mi][ni][1]; bi[lo] = ce + 1; }
                if (c[mi][ni][2] > bv[hi]) { bv[hi] = c[mi][ni][2]; bi[hi] = ce; }
                if (c[mi][ni][3] > bv[hi]) { bv[hi] = c[mi][ni][3]; bi[hi] = ce + 1; }
            }
        }
        __syncthreads();
    }

    // quad shuffle reduce (lanes sharing a row differ only in q)
#pragma unroll
    for (int e = 0; e < 8; e++) {
#pragma unroll
        for (int off = 1; off <= 2; off <<= 1) {
            float ov = __shfl_xor_sync(0xffffffffu, bv[e], off);
            int   oi = __shfl_xor_sync(0xffffffffu, bi[e], off);
            if (ov > bv[e] || (ov == bv[e] && oi < bi[e])) { bv[e] = ov; bi[e] = oi; }
        }
    }

    float* sval = (float*)dsm;            // [128][4]
    int*   sidx = (int*)(dsm + 2048);     // [128][4]
    if (q == 0) {
#pragma unroll
        for (int e = 0; e < 8; e++) {
            int r = wm + 16 * (e >> 1) + 8 * (e & 1) + g;
            sval[r * 4 + (w >> 1)] = bv[e];
            sidx[r * 4 + (w >> 1)] = bi[e];
        }
    }
    __syncthreads();
    if (tid < 128) {
        float v = sval[tid * 4];
        int   i2 = sidx[tid * 4];
#pragma unroll
        for (int wg = 1; wg < 4; wg++) {
            float ov = sval[tid * 4 + wg];
            int   oi = sidx[tid * 4 + wg];
            if (ov > v || (ov == v && oi < i2)) { v = ov; i2 = oi; }
        }
        int n = tile * BM + tid;
        g_idx_buf[n] = i2;
        out[O_IDX + n] = (float)i2;
    }
}

// ---------------- kernel: gather + loss + histogram ----------------------
__global__ void __launch_bounds__(256)
vq_gather(const float* __restrict__ z, const float* __restrict__ cb,
          float* __restrict__ out) {
    __shared__ float zq_s[128][65];
    __shared__ int   ids[128];
    __shared__ float wsum[8];
    const int tid = threadIdx.x;
    const int n0 = blockIdx.x * BM;
    const int b  = n0 >> 12;
    const int p0 = n0 & 4095;

    if (tid < 128) {
        int id = g_idx_buf[n0 + tid];
        ids[tid] = id;
        atomicAdd(&g_counts[id], 1);
    }
    __syncthreads();
    {
        int row = tid >> 1, h = tid & 1;
        const float4* src = (const float4*)(cb + (size_t)ids[row] * CDIM + h * 32);
#pragma unroll
        for (int t = 0; t < 8; t++) {
            float4 v = src[t];
            int c = h * 32 + t * 4;
            zq_s[row][c] = v.x; zq_s[row][c + 1] = v.y;
            zq_s[row][c + 2] = v.z; zq_s[row][c + 3] = v.w;
        }
    }
    __syncthreads();

    int i  = tid & 127;
    int c0 = tid >> 7;
    const float* zsrc = z + ((size_t)b * CDIM) * 4096 + p0;
    float* od = out + ((size_t)b * CDIM) * 4096 + p0;
    float lsum = 0.0f;
#pragma unroll
    for (int s = 0; s < 32; s++) {
        int c = c0 + 2 * s;
        float v  = zq_s[i][c];
        float zv = zsrc[(size_t)c * 4096 + i];
        float d  = v - zv;
        lsum += d * d;
        od[(size_t)c * 4096 + i] = v;
    }
    for (int o = 16; o > 0; o >>= 1) lsum += __shfl_down_sync(0xffffffffu, lsum, o);
    if ((tid & 31) == 0) wsum[tid >> 5] = lsum;
    __syncthreads();
    if (tid == 0) {
        float t = 0.0f;
#pragma unroll
        for (int ww = 0; ww < 8; ww++) t += wsum[ww];
        atomicAdd(&g_sumsq, t);
    }
}

// ---------------- kernel: scalars ----------------------------------------
__global__ void vq_final(float* __restrict__ out) {
    __shared__ float red[256];
    const int tid = threadIdx.x;
    float h = 0.0f;
    for (int i = tid; i < N_CODES; i += 256) {
        float e = (float)g_counts[i] * (1.0f / 65536.0f);
        h -= e * logf(e + 1e-10f);
    }
    red[tid] = h;
    __syncthreads();
    for (int o = 128; o > 0; o >>= 1) {
        if (tid < o) red[tid] += red[tid + o];
        __syncthreads();
    }
    if (tid == 0) {
        out[O_LOSS] = 1.25f * g_sumsq / 4194304.0f;
        out[O_PERP] = expf(red[0]);
    }
}

extern "C" void kernel_launch(void* const* d_in, const int* in_sizes, int n_in,
                              void* d_out, int out_size) {
    const float* z  = (const float*)d_in[0];
    const float* cb = (const float*)d_in[1];
    if (n_in >= 2 && in_sizes[0] == N_CODES * CDIM) {
        z  = (const float*)d_in[1];
        cb = (const float*)d_in[0];
    }
    float* out = (float*)d_out;

    cudaFuncSetAttribute(vq_mma, cudaFuncAttributeMaxDynamicSharedMemorySize,
                         DSMEM_REQ);

    vq_split_z<<<N_TILES, 128>>>(z);
    vq_split_cb<<<E_TILES, 128>>>(cb);
    vq_init<<<1, 256>>>();
    vq_mma<<<N_TILES, 256, DSMEM_REQ>>>(out);
    vq_gather<<<N_TILES, 256>>>(z, cb, out);
    vq_final<<<1, 256>>>(out);
    (void)out_size;
}

// round 9
// speedup vs baseline: 1.5915x; 1.0449x over previous
#include <cuda_runtime.h>
#include <cuda_bf16.h>
#include <stdint.h>
#include <math.h>
#include <string.h>

// Problem constants
#define N_ROWS 65536      // B*H*W = 16*64*64
#define N_CODES 2048
#define CDIM 64
#define BM 128
#define N_TILES (N_ROWS / BM)      // 512
#define E_TILES (N_CODES / BM)     // 16
#define NCHUNK 32                  // 64-code chunks

// Output layout: concat(z_q_out[B,C,H,W], loss, perplexity, indices) as fp32
#define O_LOSS 4194304
#define O_PERP 4194305
#define O_IDX  4194306

// smem geometry: plain row-major bf16 rows (128B data) padded to 144B so
// ldmatrix 8-row phases hit distinct 4-bank groups.
#define ROWB 144
#define PLANE_A (128 * ROWB)        // 18432 B
#define PLANE_B (64 * ROWB)         // 9216 B
#define A_BYTES (3 * PLANE_A)       // 55296
#define DSMEM_REQ (A_BYTES + 6 * PLANE_B)   // 110592 -> 2 CTAs/SM

// ---------------- scratch (device globals; no allocations allowed) --------
__device__ int   g_idx_buf[N_ROWS];
__device__ int   g_counts[N_CODES];
__device__ float g_sumsq;

// bf16 split planes, dense row-major: uint4 index = row*8 + kgroup
__device__ uint4 g_z0[N_TILES * 1024];
__device__ uint4 g_z1[N_TILES * 1024];
__device__ uint4 g_z2[N_TILES * 1024];
__device__ uint4 g_e0[E_TILES * 1024];
__device__ uint4 g_e1[E_TILES * 1024];
__device__ uint4 g_e2[E_TILES * 1024];

// ---------------- helpers -------------------------------------------------
__device__ __forceinline__ uint32_t smem_u32(const void* p) {
    uint32_t a;
    asm("{ .reg .u64 t; cvta.to.shared.u64 t, %1; cvt.u32.u64 %0, t; }"
        : "=r"(a) : "l"(p));
    return a;
}

__device__ __forceinline__ void cp16(uint32_t dst, const void* src) {
    asm volatile("cp.async.cg.shared.global [%0], [%1], 16;"
                 :: "r"(dst), "l"(src) : "memory");
}
#define CP_COMMIT() asm volatile("cp.async.commit_group;" ::: "memory")
#define CP_WAIT1()  asm volatile("cp.async.wait_group 1;" ::: "memory")
#define CP_WAIT0()  asm volatile("cp.async.wait_group 0;" ::: "memory")

__device__ __forceinline__ void ldm4(uint32_t* r, uint32_t addr) {
    asm volatile("ldmatrix.sync.aligned.m8n8.x4.shared.b16 {%0,%1,%2,%3}, [%4];"
                 : "=r"(r[0]), "=r"(r[1]), "=r"(r[2]), "=r"(r[3]) : "r"(addr));
}

#define MMA16816(cc, a0, a1, a2, a3, bb0, bb1) \
    asm("mma.sync.aligned.m16n8k16.row.col.f32.bf16.bf16.f32 " \
        "{%0,%1,%2,%3}, {%4,%5,%6,%7}, {%8,%9}, {%0,%1,%2,%3};" \
        : "+f"((cc)[0]), "+f"((cc)[1]), "+f"((cc)[2]), "+f"((cc)[3]) \
        : "r"(a0), "r"(a1), "r"(a2), "r"(a3), "r"(bb0), "r"(bb1))

// ---------------- bf16 triple split --------------------------------------
__device__ __forceinline__ void split3(float v, unsigned short& u0,
                                       unsigned short& u1, unsigned short& u2) {
    __nv_bfloat16 h0 = __float2bfloat16(v);
    float r1 = v - __bfloat162float(h0);
    __nv_bfloat16 h1 = __float2bfloat16(r1);
    float r2 = r1 - __bfloat162float(h1);
    __nv_bfloat16 h2 = __float2bfloat16(r2);
    memcpy(&u0, &h0, 2); memcpy(&u1, &h1, 2); memcpy(&u2, &h2, 2);
}
__device__ __forceinline__ uint32_t pack2(unsigned short lo, unsigned short hi) {
    return (uint32_t)lo | ((uint32_t)hi << 16);
}

// ---------------- kernel: split z (plain row-major) ----------------------
__global__ void __launch_bounds__(128)
vq_split_z(const float* __restrict__ z) {
    __shared__ float s[64][129];
    const int tile = blockIdx.x;
    const int n0 = tile * BM;
    const int b = n0 >> 12, p0 = n0 & 4095;
    const float* src = z + ((size_t)b * CDIM) * 4096 + p0;
    const int i = threadIdx.x;
#pragma unroll 8
    for (int c = 0; c < 64; c++) s[c][i] = src[(size_t)c * 4096 + i];
    __syncthreads();

#pragma unroll
    for (int j = 0; j < 8; j++) {
        unsigned short u0[8], u1[8], u2[8];
#pragma unroll
        for (int q = 0; q < 8; q++) split3(s[j * 8 + q][i], u0[q], u1[q], u2[q]);
        int idx = tile * 1024 + i * 8 + j;
        g_z0[idx] = make_uint4(pack2(u0[0], u0[1]), pack2(u0[2], u0[3]),
                               pack2(u0[4], u0[5]), pack2(u0[6], u0[7]));
        g_z1[idx] = make_uint4(pack2(u1[0], u1[1]), pack2(u1[2], u1[3]),
                               pack2(u1[4], u1[5]), pack2(u1[6], u1[7]));
        g_z2[idx] = make_uint4(pack2(u2[0], u2[1]), pack2(u2[2], u2[3]),
                               pack2(u2[4], u2[5]), pack2(u2[6], u2[7]));
    }
}

// ---------------- kernel: split codebook (plain row-major) ---------------
__global__ void __launch_bounds__(128)
vq_split_cb(const float* __restrict__ cb) {
    const int tile = blockIdx.x;
    const int i = threadIdx.x;
    float v[64];
    const float4* src = (const float4*)(cb + (size_t)(tile * BM + i) * CDIM);
#pragma unroll
    for (int t = 0; t < 16; t++) {
        float4 x = src[t];
        v[t * 4] = x.x; v[t * 4 + 1] = x.y; v[t * 4 + 2] = x.z; v[t * 4 + 3] = x.w;
    }
#pragma unroll
    for (int j = 0; j < 8; j++) {
        unsigned short u0[8], u1[8], u2[8];
#pragma unroll
        for (int q = 0; q < 8; q++) split3(v[j * 8 + q], u0[q], u1[q], u2[q]);
        int idx = tile * 1024 + i * 8 + j;
        g_e0[idx] = make_uint4(pack2(u0[0], u0[1]), pack2(u0[2], u0[3]),
                               pack2(u0[4], u0[5]), pack2(u0[6], u0[7]));
        g_e1[idx] = make_uint4(pack2(u1[0], u1[1]), pack2(u1[2], u1[3]),
                               pack2(u1[4], u1[5]), pack2(u1[6], u1[7]));
        g_e2[idx] = make_uint4(pack2(u2[0], u2[1]), pack2(u2[2], u2[3]),
                               pack2(u2[4], u2[5]), pack2(u2[6], u2[7]));
    }
}

__global__ void vq_init() {
    for (int i = threadIdx.x; i < N_CODES; i += blockDim.x) g_counts[i] = 0;
    if (threadIdx.x == 0) g_sumsq = 0.0f;
}

// ---------------- kernel: mma.sync GEMM + per-row argmax -----------------
// Emulated fp32 via bf16x3: logits = z0e0+z0e1+z1e0+z1e1+z0e2+z2e0, single
// accumulator set. 8 warps, warp tile 64x16, 64-code chunks, 2 CTAs/SM.
__global__ void __launch_bounds__(256, 2)
vq_mma(float* __restrict__ out) {
    extern __shared__ char dsm[];
    const int tid = threadIdx.x;
    const int w = tid >> 5, lane = tid & 31;
    const int g = lane >> 2, q = lane & 3;
    const int mrow = lane & 7, quad = lane >> 3;
    const int wm = (w & 1) * 64, wn = (w >> 1) * 16;
    const int tile = blockIdx.x;

    const uint32_t sA = smem_u32(dsm);
    const uint32_t sB = sA + A_BYTES;

    // ldmatrix per-thread intra-plane offsets
    const uint32_t aoff = (uint32_t)(wm + mrow + 8 * (quad & 1)) * ROWB
                        + 16 * (quad >> 1);
    const uint32_t boff = (uint32_t)(wn + mrow + 8 * (quad >> 1)) * ROWB
                        + 16 * (quad & 1);

    // prologue: A tiles + B chunk 0 (one commit group)
    {
        const uint4* zs[3] = {g_z0 + tile * 1024, g_z1 + tile * 1024,
                              g_z2 + tile * 1024};
        for (int t = tid; t < 3072; t += 256) {
            int pl = t >> 10, rem = t & 1023, r = rem >> 3, j = rem & 7;
            cp16(sA + pl * PLANE_A + r * ROWB + j * 16, zs[pl] + rem);
        }
        const uint4* es[3] = {g_e0, g_e1, g_e2};
        for (int t = tid; t < 1536; t += 256) {
            int pl = t >> 9, rem = t & 511, r = rem >> 3, j = rem & 7;
            cp16(sB + pl * PLANE_B + r * ROWB + j * 16, es[pl] + rem);
        }
        CP_COMMIT();
    }

    float bv[8];
    int   bi[8];
#pragma unroll
    for (int e = 0; e < 8; e++) { bv[e] = -3.4e38f; bi[e] = 0; }

    for (int ch = 0; ch < NCHUNK; ch++) {
        if (ch < NCHUNK - 1) {   // prefetch next B chunk into other buffer
            const uint4* es[3] = {g_e0 + (ch + 1) * 512, g_e1 + (ch + 1) * 512,
                                  g_e2 + (ch + 1) * 512};
            uint32_t dstb = sB + ((ch + 1) & 1) * (3 * PLANE_B);
            for (int t = tid; t < 1536; t += 256) {
                int pl = t >> 9, rem = t & 511, r = rem >> 3, j = rem & 7;
                cp16(dstb + pl * PLANE_B + r * ROWB + j * 16, es[pl] + rem);
            }
            CP_COMMIT();
            CP_WAIT1();
        } else {
            CP_WAIT0();
        }
        __syncthreads();

        const uint32_t bB = sB + (ch & 1) * (3 * PLANE_B);

        float c[4][2][4];
#pragma unroll
        for (int mi = 0; mi < 4; mi++)
#pragma unroll
            for (int ni = 0; ni < 2; ni++)
#pragma unroll
                for (int e = 0; e < 4; e++) c[mi][ni][e] = 0.0f;

#pragma unroll
        for (int ks = 0; ks < 4; ks++) {
            const uint32_t koff = ks * 32;
            // B fragments: 1 ldm4 per plane covers 16 codes x k16
            uint32_t B0[4], B1[4], B2[4];
            ldm4(B0, bB + 0 * PLANE_B + boff + koff);
            ldm4(B1, bB + 1 * PLANE_B + boff + koff);
            ldm4(B2, bB + 2 * PLANE_B + boff + koff);

            uint32_t A[16];
            // z0: products with e0, e1, e2
            ldm4(A,      sA + 0 * PLANE_A + aoff + koff);
            ldm4(A + 4,  sA + 0 * PLANE_A + aoff + koff + 16 * ROWB);
            ldm4(A + 8,  sA + 0 * PLANE_A + aoff + koff + 32 * ROWB);
            ldm4(A + 12, sA + 0 * PLANE_A + aoff + koff + 48 * ROWB);
#pragma unroll
            for (int mi = 0; mi < 4; mi++)
#pragma unroll
                for (int ni = 0; ni < 2; ni++) {
                    MMA16816(c[mi][ni], A[mi*4], A[mi*4+1], A[mi*4+2], A[mi*4+3],
                             B0[ni*2], B0[ni*2+1]);
                    MMA16816(c[mi][ni], A[mi*4], A[mi*4+1], A[mi*4+2], A[mi*4+3],
                             B1[ni*2], B1[ni*2+1]);
                    MMA16816(c[mi][ni], A[mi*4], A[mi*4+1], A[mi*4+2], A[mi*4+3],
                             B2[ni*2], B2[ni*2+1]);
                }
            // z1: products with e0, e1
            ldm4(A,      sA + 1 * PLANE_A + aoff + koff);
            ldm4(A + 4,  sA + 1 * PLANE_A + aoff + koff + 16 * ROWB);
            ldm4(A + 8,  sA + 1 * PLANE_A + aoff + koff + 32 * ROWB);
            ldm4(A + 12, sA + 1 * PLANE_A + aoff + koff + 48 * ROWB);
#pragma unroll
            for (int mi = 0; mi < 4; mi++)
#pragma unroll
                for (int ni = 0; ni < 2; ni++) {
                    MMA16816(c[mi][ni], A[mi*4], A[mi*4+1], A[mi*4+2], A[mi*4+3],
                             B0[ni*2], B0[ni*2+1]);
                    MMA16816(c[mi][ni], A[mi*4], A[mi*4+1], A[mi*4+2], A[mi*4+3],
                             B1[ni*2], B1[ni*2+1]);
                }
            // z2: product with e0
            ldm4(A,      sA + 2 * PLANE_A + aoff + koff);
            ldm4(A + 4,  sA + 2 * PLANE_A + aoff + koff + 16 * ROWB);
            ldm4(A + 8,  sA + 2 * PLANE_A + aoff + koff + 32 * ROWB);
            ldm4(A + 12, sA + 2 * PLANE_A + aoff + koff + 48 * ROWB);
#pragma unroll
            for (int mi = 0; mi < 4; mi++)
#pragma unroll
                for (int ni = 0; ni < 2; ni++)
                    MMA16816(c[mi][ni], A[mi*4], A[mi*4+1], A[mi*4+2], A[mi*4+3],
                             B0[ni*2], B0[ni*2+1]);
        }

        // fold chunk into running argmax (ascending candidate order -> strict >)
        const int cb0 = ch * 64 + wn + 2 * q;
#pragma unroll
        for (int mi = 0; mi < 4; mi++) {
            const int lo = mi * 2, hi = mi * 2 + 1;
#pragma unroll
            for (int ni = 0; ni < 2; ni++) {
                int ce = cb0 + 8 * ni;
                if (c[mi][ni][0] > bv[lo]) { bv[lo] = c[mi][ni][0]; bi[lo] = ce; }
                if (c[mi][ni][1] > bv[lo]) { bv[lo] = c[mi][ni][1]; bi[lo] = ce + 1; }
                if (c[mi][ni][2] > bv[hi]) { bv[hi] = c[mi][ni][2]; bi[hi] = ce; }
                if (c[mi][ni][3] > bv[hi]) { bv[hi] = c[mi][ni][3]; bi[hi] = ce + 1; }
            }
        }
        __syncthreads();
    }

    // quad shuffle reduce (lanes sharing a row differ only in q)
#pragma unroll
    for (int e = 0; e < 8; e++) {
#pragma unroll
        for (int off = 1; off <= 2; off <<= 1) {
            float ov = __shfl_xor_sync(0xffffffffu, bv[e], off);
            int   oi = __shfl_xor_sync(0xffffffffu, bi[e], off);
            if (ov > bv[e] || (ov == bv[e] && oi < bi[e])) { bv[e] = ov; bi[e] = oi; }
        }
    }

    float* sval = (float*)dsm;            // [128][4]
    int*   sidx = (int*)(dsm + 2048);     // [128][4]
    if (q == 0) {
#pragma unroll
        for (int e = 0; e < 8; e++) {
            int r = wm + 16 * (e >> 1) + 8 * (e & 1) + g;
            sval[r * 4 + (w >> 1)] = bv[e];
            sidx[r * 4 + (w >> 1)] = bi[e];
        }
    }
    __syncthreads();
    if (tid < 128) {
        float v = sval[tid * 4];
        int   i2 = sidx[tid * 4];
#pragma unroll
        for (int wg = 1; wg < 4; wg++) {
            float ov = sval[tid * 4 + wg];
            int   oi = sidx[tid * 4 + wg];
            if (ov > v || (ov == v && oi < i2)) { v = ov; i2 = oi; }
        }
        int n = tile * BM + tid;
        g_idx_buf[n] = i2;
        out[O_IDX + n] = (float)i2;
    }
}

// ---------------- kernel: gather + loss + histogram ----------------------
__global__ void __launch_bounds__(256)
vq_gather(const float* __restrict__ z, const float* __restrict__ cb,
          float* __restrict__ out) {
    __shared__ float zq_s[128][65];
    __shared__ int   ids[128];
    __shared__ float wsum[8];
    const int tid = threadIdx.x;
    const int n0 = blockIdx.x * BM;
    const int b  = n0 >> 12;
    const int p0 = n0 & 4095;

    if (tid < 128) {
        int id = g_idx_buf[n0 + tid];
        ids[tid] = id;
        atomicAdd(&g_counts[id], 1);
    }
    __syncthreads();
    {
        int row = tid >> 1, h = tid & 1;
        const float4* src = (const float4*)(cb + (size_t)ids[row] * CDIM + h * 32);
#pragma unroll
        for (int t = 0; t < 8; t++) {
            float4 v = src[t];
            int c = h * 32 + t * 4;
            zq_s[row][c] = v.x; zq_s[row][c + 1] = v.y;
            zq_s[row][c + 2] = v.z; zq_s[row][c + 3] = v.w;
        }
    }
    __syncthreads();

    int i  = tid & 127;
    int c0 = tid >> 7;
    const float* zsrc = z + ((size_t)b * CDIM) * 4096 + p0;
    float* od = out + ((size_t)b * CDIM) * 4096 + p0;
    float lsum = 0.0f;
#pragma unroll
    for (int s = 0; s < 32; s++) {
        int c = c0 + 2 * s;
        float v  = zq_s[i][c];
        float zv = zsrc[(size_t)c * 4096 + i];
        float d  = v - zv;
        lsum += d * d;
        od[(size_t)c * 4096 + i] = v;
    }
    for (int o = 16; o > 0; o >>= 1) lsum += __shfl_down_sync(0xffffffffu, lsum, o);
    if ((tid & 31) == 0) wsum[tid >> 5] = lsum;
    __syncthreads();
    if (tid == 0) {
        float t = 0.0f;
#pragma unroll
        for (int ww = 0; ww < 8; ww++) t += wsum[ww];
        atomicAdd(&g_sumsq, t);
    }
}

// ---------------- kernel: scalars ----------------------------------------
__global__ void vq_final(float* __restrict__ out) {
    __shared__ float red[256];
    const int tid = threadIdx.x;
    float h = 0.0f;
    for (int i = tid; i < N_CODES; i += 256) {
        float e = (float)g_counts[i] * (1.0f / 65536.0f);
        h -= e * logf(e + 1e-10f);
    }
    red[tid] = h;
    __syncthreads();
    for (int o = 128; o > 0; o >>= 1) {
        if (tid < o) red[tid] += red[tid + o];
        __syncthreads();
    }
    if (tid == 0) {
        out[O_LOSS] = 1.25f * g_sumsq / 4194304.0f;
        out[O_PERP] = expf(red[0]);
    }
}

extern "C" void kernel_launch(void* const* d_in, const int* in_sizes, int n_in,
                              void* d_out, int out_size) {
    const float* z  = (const float*)d_in[0];
    const float* cb = (const float*)d_in[1];
    if (n_in >= 2 && in_sizes[0] == N_CODES * CDIM) {
        z  = (const float*)d_in[1];
        cb = (const float*)d_in[0];
    }
    float* out = (float*)d_out;

    cudaFuncSetAttribute(vq_mma, cudaFuncAttributeMaxDynamicSharedMemorySize,
                         DSMEM_REQ);

    vq_split_z<<<N_TILES, 128>>>(z);
    vq_split_cb<<<E_TILES, 128>>>(cb);
    vq_init<<<1, 256>>>();
    vq_mma<<<N_TILES, 256, DSMEM_REQ>>>(out);
    vq_gather<<<N_TILES, 256>>>(z, cb, out);
    vq_final<<<1, 256>>>(out);
    (void)out_size;
}